// round 8
// baseline (speedup 1.0000x reference)
#include <cuda_runtime.h>
#include <cstdint>

// Problem constants
#define NN   24
#define EE   96
#define BB   4
#define CC   8
#define HH   96
#define WW   96
#define KK   4
#define HW    (HH*WW)
#define CHW   (CC*HW)
#define BCHW  (BB*CHW)

// Padded activation scratch, ci-pair interleaved:
//   [gp=400][pos<PLANE][half=2]; value(ci,pos) of plane-group g at
//   ((g*4 + (ci&3))*PLANE + pos)*2 + (ci>>2). Zero border (never written).
#define PH 100
#define PW 100
#define PLANE (PH*PW)
#define NACT  (25*BB*4*PLANE*2)

// Conv-MMA tiling
#define SEGPX  384               // pixels per block (24 m16 tiles)
#define NSEG   25                // 25*384 = 9600
#define TPW    3                 // m16 tiles per warp (8 warps)
#define WINF   688               // window positions per ci (383+303+1+1)
#define PSTR2  1384              // pair stride in floats (==8 mod 32)
#define ABUF   (4*PSTR2)         // 5536 floats: activation window
#define WREG   1024              // weight floats per edge
#define EBUF   (ABUF+WREG)       // 6560 floats per stage buffer
#define PAIR4  344               // float4s per pair window (688*2/4)
#define NBLK   (NSEG*BB*NN)      // 2400 conv blocks

__device__ __align__(16) float g_act[NACT];
__device__ int   g_off[NN + 1];
__device__ int   g_elist[EE];
__device__ float g_escale[EE];
__device__ float g_postsum[NN];
__device__ unsigned int g_done;

__device__ __forceinline__ uint32_t f2tf32(float v) {
    uint32_t r;
    asm("cvt.rna.tf32.f32 %0, %1;" : "=r"(r) : "f"(v));
    return r;
}

__device__ __forceinline__ void mma_tf32(float* d, uint32_t a0, uint32_t a1,
                                         uint32_t a2, uint32_t a3,
                                         uint32_t b0, uint32_t b1) {
    asm volatile(
        "mma.sync.aligned.m16n8k8.row.col.f32.tf32.tf32.f32 "
        "{%0,%1,%2,%3}, {%4,%5,%6,%7}, {%8,%9}, {%0,%1,%2,%3};"
        : "+f"(d[0]), "+f"(d[1]), "+f"(d[2]), "+f"(d[3])
        : "r"(a0), "r"(a1), "r"(a2), "r"(a3), "r"(b0), "r"(b1));
}

__device__ __forceinline__ void cpa16(uint32_t dst, const void* src) {
    asm volatile("cp.async.cg.shared.global [%0], [%1], 16;"
                 :: "r"(dst), "l"(src));
}
__device__ __forceinline__ uint32_t smem_u32(const void* p) {
    uint32_t a;
    asm("{ .reg .u64 t; cvta.to.shared.u64 t, %1; cvt.u32.u64 %0, t; }"
        : "=r"(a) : "l"(p));
    return a;
}

// ---------------------------------------------------------------------------
// Activation precompute (+ prep in block (0,0)). grid = (9, 400 pair-planes).
// ---------------------------------------------------------------------------
__global__ __launch_bounds__(256)
void act_prep_kernel(const float* __restrict__ states,
                     const int* __restrict__ dst,
                     const float* __restrict__ plast) {
    const int t = threadIdx.x;
    if (blockIdx.x == 0 && blockIdx.y == 0) {
        __shared__ int cnt[NN];
        __shared__ int fill[NN];
        if (t < NN) { cnt[t] = 0; g_postsum[t] = 0.0f; }
        __syncthreads();
        if (t < EE) atomicAdd(&cnt[dst[t]], 1);
        __syncthreads();
        if (t == 0) {
            int off = 0;
            for (int n = 0; n < NN; ++n) { g_off[n] = off; fill[n] = off; off += cnt[n]; }
            g_off[NN] = off;
        }
        __syncthreads();
        if (t < EE) {
            int d = dst[t];
            int pos = atomicAdd(&fill[d], 1);
            g_elist[pos] = t;
            int deg = cnt[d] > 0 ? cnt[d] : 1;
            g_escale[t] = plast[t] / (float)deg;
        }
    }
    const int gp = blockIdx.y;              // g*4 + pair
    const int g = gp >> 2;
    const int pair = gp & 3;
    const int idx4 = blockIdx.x * 256 + t;  // 0..2303
    const int r = idx4 / 24;
    const int c4 = idx4 - r * 24;

    const size_t base = (size_t)(g * CC + pair) * HW + r * WW + c4 * 4;
    const float4 zl = *reinterpret_cast<const float4*>(states + base);
    const float4 zh = *reinterpret_cast<const float4*>(states + base + 4 * HW);

    float l0 = __uint_as_float(f2tf32(1.0f / (1.0f + __expf(-zl.x))));
    float l1 = __uint_as_float(f2tf32(1.0f / (1.0f + __expf(-zl.y))));
    float l2 = __uint_as_float(f2tf32(1.0f / (1.0f + __expf(-zl.z))));
    float l3 = __uint_as_float(f2tf32(1.0f / (1.0f + __expf(-zl.w))));
    float h0 = __uint_as_float(f2tf32(1.0f / (1.0f + __expf(-zh.x))));
    float h1 = __uint_as_float(f2tf32(1.0f / (1.0f + __expf(-zh.y))));
    float h2 = __uint_as_float(f2tf32(1.0f / (1.0f + __expf(-zh.z))));
    float h3 = __uint_as_float(f2tf32(1.0f / (1.0f + __expf(-zh.w))));

    float2* op = reinterpret_cast<float2*>(
        g_act + ((size_t)gp * PLANE + (r + 1) * PW + 1 + c4 * 4) * 2);
    op[0] = make_float2(l0, h0);
    op[1] = make_float2(l1, h1);
    op[2] = make_float2(l2, h2);
    op[3] = make_float2(l3, h3);
}

// ---------------------------------------------------------------------------
// Conv via warp MMA (tf32). Double-buffered cp.async stages window + weights.
// grid = (NSEG, B, N), 256 threads, 4 blocks/SM.
// ---------------------------------------------------------------------------
extern __shared__ float s_dyn[];

__global__ __launch_bounds__(256, 4)
void conv_mma_kernel(const float* __restrict__ weights,
                     const int* __restrict__ src,
                     const float* __restrict__ plast,
                     const int* __restrict__ dst,
                     float* __restrict__ out,
                     float* __restrict__ outp) {
    const int seg = blockIdx.x;
    const int b = blockIdx.y;
    const int n = blockIdx.z;
    const int qbase = seg * SEGPX;

    __shared__ float s_red[8];
    __shared__ int s_last;
    float* s_win = s_dyn;                          // [2][EBUF]
    const uint32_t s_win_u32 = smem_u32(s_win);

    const int t = threadIdx.x;
    const int w = t >> 5;
    const int l = t & 31;
    const int gid = l >> 2;
    const int tig = l & 3;

    float d[TPW][4];
#pragma unroll
    for (int u = 0; u < TPW; ++u)
#pragma unroll
        for (int j = 0; j < 4; ++j) d[u][j] = 0.0f;

    const int ebeg = g_off[n];
    const int eend = g_off[n + 1];

    auto stage = [&](int e, uint32_t dbase) {
        const int s = __ldg(&src[e]);
        const float4* ap = reinterpret_cast<const float4*>(
            g_act + ((size_t)(s * BB + b) * 4 * PLANE + qbase) * 2);
#pragma unroll
        for (int pair = 0; pair < 4; ++pair)
            for (int i = t; i < PAIR4; i += 256)
                cpa16(dbase + (pair * PSTR2 + i * 4) * 4,
                      ap + pair * (PLANE / 2) + i);
        const float4* wp = reinterpret_cast<const float4*>(
            weights + (size_t)e * WREG);
        cpa16(dbase + (ABUF + t * 4) * 4, wp + t);
        asm volatile("cp.async.commit_group;");
    };

    stage(g_elist[ebeg], s_win_u32);

    for (int ei = ebeg; ei < eend; ++ei) {
        const int p = (ei - ebeg) & 1;
        const float esc = g_escale[g_elist[ei]];

        asm volatile("cp.async.wait_group 0;");
        __syncthreads();

        if (ei + 1 < eend)
            stage(g_elist[ei + 1], s_win_u32 + (1 - p) * (EBUF * 4));

        const float* fbase = s_win + p * EBUF + tig * PSTR2 + gid * 2;
        const float* wsm = s_win + p * EBUF + ABUF;
        const int wo0 = (gid * CC + tig) << 4;
        const int wo1 = (gid * CC + tig + 4) << 4;
#pragma unroll
        for (int ky = 0; ky < KK; ++ky) {
            const float4 w0 = *reinterpret_cast<const float4*>(wsm + wo0 + ky * 4);
            const float4 w1 = *reinterpret_cast<const float4*>(wsm + wo1 + ky * 4);
            uint32_t bk0[4], bk1[4];
            bk0[0] = f2tf32(w0.x * esc); bk0[1] = f2tf32(w0.y * esc);
            bk0[2] = f2tf32(w0.z * esc); bk0[3] = f2tf32(w0.w * esc);
            bk1[0] = f2tf32(w1.x * esc); bk1[1] = f2tf32(w1.y * esc);
            bk1[2] = f2tf32(w1.z * esc); bk1[3] = f2tf32(w1.w * esc);
#pragma unroll
            for (int kx = 0; kx < KK; ++kx) {
                const int o2 = (ky * PW + kx) * 2;
#pragma unroll
                for (int u = 0; u < TPW; ++u) {
                    const int lq2 = (w * TPW + u) * 32;
                    const float2 v01 = *reinterpret_cast<const float2*>(
                        fbase + lq2 + o2);
                    const float2 v23 = *reinterpret_cast<const float2*>(
                        fbase + lq2 + o2 + 16);
                    mma_tf32(d[u],
                             __float_as_uint(v01.x), __float_as_uint(v23.x),
                             __float_as_uint(v01.y), __float_as_uint(v23.y),
                             bk0[kx], bk1[kx]);
                }
            }
        }
    }

    // Epilogue: store future + fused sigmoid sum
    float ls = 0.0f;
    const int co0 = tig * 2;
    float* outn = out + (size_t)((n * BB + b) * CC) * HW;
#pragma unroll
    for (int u = 0; u < TPW; ++u) {
        const int lq = qbase + (w * TPW + u) * 16;
#pragma unroll
        for (int h = 0; h < 2; ++h) {
            const int q = lq + gid + h * 8;
            const int y = q / PW;
            const int x = q - y * PW;
            if (x < WW) {
                float v0 = d[u][h * 2 + 0];
                float v1 = d[u][h * 2 + 1];
                float* ob = outn + y * WW + x;
                ob[(size_t)co0 * HW] = v0;
                ob[(size_t)(co0 + 1) * HW] = v1;
                ls += 1.0f / (1.0f + __expf(-v0));
                ls += 1.0f / (1.0f + __expf(-v1));
            }
        }
    }
#pragma unroll
    for (int o = 16; o > 0; o >>= 1) ls += __shfl_down_sync(0xffffffffu, ls, o);
    if (l == 0) s_red[w] = ls;
    __syncthreads();
    if (t == 0) {
        float sum = 0.0f;
#pragma unroll
        for (int i = 0; i < 8; ++i) sum += s_red[i];
        atomicAdd(&g_postsum[n], sum);
        __threadfence();
        unsigned prev = atomicAdd(&g_done, 1u);
        s_last = (prev == NBLK - 1) ? 1 : 0;
        if (s_last) g_done = 0;
    }
    __syncthreads();
    if (s_last && t < EE) {
        float mean = g_postsum[dst[t]] * (1.0f / (float)BCHW);
        outp[t] = plast[t] + 0.1f * (mean - 0.5f);
    }
}

// ---------------------------------------------------------------------------
extern "C" void kernel_launch(void* const* d_in, const int* in_sizes, int n_in,
                              void* d_out, int out_size) {
    const float* states  = (const float*)d_in[0];
    const float* weights = (const float*)d_in[1];
    const float* plast   = (const float*)d_in[2];
    const int*   src     = (const int*)d_in[3];
    const int*   dst     = (const int*)d_in[4];
    float* out = (float*)d_out;

    dim3 agrid(9, 400);
    act_prep_kernel<<<agrid, 256>>>(states, dst, plast);

    static int smem_set = 0;
    const int smem_bytes = 2 * EBUF * 4;     // 52480
    if (!smem_set) {
        cudaFuncSetAttribute(conv_mma_kernel,
                             cudaFuncAttributeMaxDynamicSharedMemorySize,
                             smem_bytes);
        smem_set = 1;
    }
    dim3 grid(NSEG, BB, NN);
    conv_mma_kernel<<<grid, 256, smem_bytes>>>(weights, src, plast, dst, out,
                                               out + (out_size - EE));
}

// round 9
// speedup vs baseline: 1.9475x; 1.9475x over previous
#include <cuda_runtime.h>
#include <cuda_fp16.h>
#include <cstdint>

// Problem constants
#define NN   24
#define EE   96
#define BB   4
#define CC   8
#define HH   96
#define WW   96
#define KK   4
#define HW    (HH*WW)
#define CHW   (CC*HW)
#define BCHW  (BB*CHW)

// Padded fp16 activation scratch, ci-pair interleaved:
//   u32 word at [(group*4 + cp)*PLANE + pos] = half2(act(2cp,pos), act(2cp+1,pos))
//   group = node*BB + b (0..99). Zero border (never written).
#define PH 100
#define PW 100
#define PLANE (PH*PW)            // 10000 words
#define NACTW (25*BB*4*PLANE)    // 4,000,000 u32

// Conv-MMA tiling (fp16 m16n8k16, 2 kx taps per MMA)
#define SEGPX  640               // pixels per block (40 m16 tiles)
#define NSEG   15                // 15*640 = 9600
#define TPW    5                 // m16 tiles per warp (8 warps)
#define WINW   944               // window words per cpair plane
#define PSTR   968               // cpair stride in words (==8 mod 32)
#define ABUF   (4*PSTR)          // 3872 words per stage buffer
#define PAIR4  236               // float4 (16B) chunks per cpair window
#define NBLK   (NSEG*BB*NN)      // 1440 conv blocks

__device__ __align__(16) unsigned int g_act[NACTW];
__device__ __align__(16) unsigned int g_bpack[EE * 32 * 16];  // per-lane B frags
__device__ int   g_off[NN + 1];
__device__ int   g_elist[EE];
__device__ float g_escale[EE];
__device__ float g_postsum[NN];
__device__ unsigned int g_done;

__device__ __forceinline__ void mma_f16(float* d, uint32_t a0, uint32_t a1,
                                        uint32_t a2, uint32_t a3,
                                        uint32_t b0, uint32_t b1) {
    asm volatile(
        "mma.sync.aligned.m16n8k16.row.col.f32.f16.f16.f32 "
        "{%0,%1,%2,%3}, {%4,%5,%6,%7}, {%8,%9}, {%0,%1,%2,%3};"
        : "+f"(d[0]), "+f"(d[1]), "+f"(d[2]), "+f"(d[3])
        : "r"(a0), "r"(a1), "r"(a2), "r"(a3), "r"(b0), "r"(b1));
}

__device__ __forceinline__ void cpa16(uint32_t dst, const void* src) {
    asm volatile("cp.async.cg.shared.global [%0], [%1], 16;"
                 :: "r"(dst), "l"(src));
}
__device__ __forceinline__ uint32_t smem_u32(const void* p) {
    uint32_t a;
    asm("{ .reg .u64 t; cvta.to.shared.u64 t, %1; cvt.u32.u64 %0, t; }"
        : "=r"(a) : "l"(p));
    return a;
}
__device__ __forceinline__ uint32_t h2pack(float lo, float hi) {
    __half2 h = __floats2half2_rn(lo, hi);   // lo -> .x (low half)
    return *reinterpret_cast<uint32_t*>(&h);
}

// ---------------------------------------------------------------------------
// Activation precompute (+ edge prep in block (0,0)). grid = (36, 400).
// Thread -> one pixel of one cpair plane: 2 f32 reads, 2 sigmoids, 1 u32 write.
// ---------------------------------------------------------------------------
__global__ __launch_bounds__(256)
void act_prep_kernel(const float* __restrict__ states,
                     const int* __restrict__ dst,
                     const float* __restrict__ plast) {
    const int t = threadIdx.x;
    if (blockIdx.x == 0 && blockIdx.y == 0) {
        __shared__ int cnt[NN];
        __shared__ int fill[NN];
        if (t < NN) { cnt[t] = 0; g_postsum[t] = 0.0f; }
        __syncthreads();
        if (t < EE) atomicAdd(&cnt[dst[t]], 1);
        __syncthreads();
        if (t == 0) {
            int off = 0;
            for (int n = 0; n < NN; ++n) { g_off[n] = off; fill[n] = off; off += cnt[n]; }
            g_off[NN] = off;
        }
        __syncthreads();
        if (t < EE) {
            int d = dst[t];
            int pos = atomicAdd(&fill[d], 1);
            g_elist[pos] = t;
            int deg = cnt[d] > 0 ? cnt[d] : 1;
            g_escale[t] = plast[t] / (float)deg;
        }
    }
    const int gp = blockIdx.y;              // group*4 + cp, 0..399
    const int grp = gp >> 2;
    const int cp = gp & 3;
    const int pix = blockIdx.x * 256 + t;   // 0..9215
    const int r = pix / 96;
    const int c = pix - r * 96;

    const size_t base = (size_t)(grp * CC + 2 * cp) * HW + r * WW + c;
    float zl = states[base];
    float zh = states[base + HW];
    float vl = 1.0f / (1.0f + __expf(-zl));
    float vh = 1.0f / (1.0f + __expf(-zh));

    g_act[(size_t)gp * PLANE + (r + 1) * PW + 1 + c] = h2pack(vl, vh);
}

// ---------------------------------------------------------------------------
// B-fragment prepack: per edge, per lane, 16 u32 half2 words in register order
// bw[ky*4 + kxp*2 + i] = half2(w[gid][2tig][ky][2kxp+i]*esc,
//                              w[gid][2tig+1][ky][2kxp+i]*esc)
// ---------------------------------------------------------------------------
__global__ void prepack_kernel(const float* __restrict__ weights) {
    const int e = blockIdx.x;
    const int l = threadIdx.x;      // 0..31
    const int g = l >> 2;
    const int tg = l & 3;
    const float esc = g_escale[e];
    const float* wg = weights + (size_t)e * (CC * CC * KK * KK);
    const float4* rA = reinterpret_cast<const float4*>(wg + (g * CC + 2 * tg) * 16);
    const float4* rB = reinterpret_cast<const float4*>(wg + (g * CC + 2 * tg + 1) * 16);
    uint32_t o[16];
#pragma unroll
    for (int ky = 0; ky < 4; ++ky) {
        float4 a = rA[ky];
        float4 b = rB[ky];
        o[ky * 4 + 0] = h2pack(a.x * esc, b.x * esc);
        o[ky * 4 + 1] = h2pack(a.y * esc, b.y * esc);
        o[ky * 4 + 2] = h2pack(a.z * esc, b.z * esc);
        o[ky * 4 + 3] = h2pack(a.w * esc, b.w * esc);
    }
    uint4* dst = reinterpret_cast<uint4*>(g_bpack + ((size_t)e * 32 + l) * 16);
#pragma unroll
    for (int j = 0; j < 4; ++j)
        dst[j] = make_uint4(o[j * 4], o[j * 4 + 1], o[j * 4 + 2], o[j * 4 + 3]);
}

// ---------------------------------------------------------------------------
// Conv via fp16 m16n8k16 MMA, permuted rows (a1==a2 shared word).
// grid = (NSEG, B, N), 256 threads, 4 blocks/SM. Dynamic smem: 2*ABUF words.
// ---------------------------------------------------------------------------
extern __shared__ unsigned int s_dynw[];

__global__ __launch_bounds__(256, 4)
void conv_mma_kernel(const int* __restrict__ src,
                     const float* __restrict__ plast,
                     const int* __restrict__ dst,
                     float* __restrict__ out,
                     float* __restrict__ outp) {
    const int seg = blockIdx.x;
    const int b = blockIdx.y;
    const int n = blockIdx.z;
    const int qbase = seg * SEGPX;

    __shared__ float s_red[8];
    __shared__ int s_last;
    unsigned int* s_win = s_dynw;                  // [2][ABUF]
    const uint32_t s_win_u32 = smem_u32(s_win);

    const int t = threadIdx.x;
    const int w = t >> 5;
    const int l = t & 31;
    const int gid = l >> 2;
    const int tig = l & 3;

    float d[TPW][4];
#pragma unroll
    for (int u = 0; u < TPW; ++u)
#pragma unroll
        for (int j = 0; j < 4; ++j) d[u][j] = 0.0f;

    const int ebeg = g_off[n];
    const int eend = g_off[n + 1];

    auto stage = [&](int e, uint32_t dbase) {
        const int s = __ldg(&src[e]);
        const uint4* ap = reinterpret_cast<const uint4*>(
            g_act + ((size_t)(s * BB + b) * 4) * PLANE + qbase);
#pragma unroll
        for (int cp = 0; cp < 4; ++cp)
            for (int i = t; i < PAIR4; i += 256)
                cpa16(dbase + (cp * PSTR + i * 4) * 4,
                      ap + cp * (PLANE / 4) + i);
        asm volatile("cp.async.commit_group;");
    };

    stage(g_elist[ebeg], s_win_u32);

    for (int ei = ebeg; ei < eend; ++ei) {
        const int p = (ei - ebeg) & 1;
        const int e = g_elist[ei];

        // B fragments from prepacked gmem (same addr across warps -> L1 hit)
        const uint4* bp = reinterpret_cast<const uint4*>(
            g_bpack + ((size_t)e * 32 + l) * 16);
        uint4 bq[4];
#pragma unroll
        for (int ky = 0; ky < 4; ++ky) bq[ky] = __ldg(&bp[ky]);

        asm volatile("cp.async.wait_group 0;");
        __syncthreads();

        if (ei + 1 < eend)
            stage(g_elist[ei + 1], s_win_u32 + (1 - p) * (ABUF * 4));

        const unsigned int* fbase = s_win + p * ABUF + tig * PSTR + 2 * gid;
#pragma unroll
        for (int ky = 0; ky < KK; ++ky) {
            const uint32_t b00 = bq[ky].x, b01 = bq[ky].y;   // kxp=0
            const uint32_t b10 = bq[ky].z, b11 = bq[ky].w;   // kxp=1
#pragma unroll
            for (int kxp = 0; kxp < 2; ++kxp) {
                const uint32_t bb0 = kxp ? b10 : b00;
                const uint32_t bb1 = kxp ? b11 : b01;
                const int o = ky * PW + kxp * 2;
#pragma unroll
                for (int u = 0; u < TPW; ++u) {
                    const unsigned int* pa = fbase + (w * TPW + u) * 16 + o;
                    const uint2 v = *reinterpret_cast<const uint2*>(pa); // a0, a1==a2
                    const uint32_t a3 = pa[2];
                    mma_f16(d[u], v.x, v.y, v.y, a3, bb0, bb1);
                }
            }
        }
    }

    // Epilogue: permuted rows -> pixel pair (q0, q0+1); store + sigmoid sum
    float ls = 0.0f;
    const int co0 = tig * 2;
    float* outn = out + (size_t)((n * BB + b) * CC) * HW;
#pragma unroll
    for (int u = 0; u < TPW; ++u) {
        const int q0 = qbase + (w * TPW + u) * 16 + 2 * gid;
        const int y = q0 / PW;
        const int x = q0 - y * PW;            // even
        if (x < WW) {                          // covers q0 and q0+1
            float v00 = d[u][0], v01 = d[u][1];   // pixel q0,   co0, co0+1
            float v10 = d[u][2], v11 = d[u][3];   // pixel q0+1, co0, co0+1
            float* ob = outn + y * WW + x;
            ob[(size_t)co0 * HW] = v00;
            ob[(size_t)(co0 + 1) * HW] = v01;
            ob[(size_t)co0 * HW + 1] = v10;
            ob[(size_t)(co0 + 1) * HW + 1] = v11;
            ls += 1.0f / (1.0f + __expf(-v00));
            ls += 1.0f / (1.0f + __expf(-v01));
            ls += 1.0f / (1.0f + __expf(-v10));
            ls += 1.0f / (1.0f + __expf(-v11));
        }
    }
#pragma unroll
    for (int o = 16; o > 0; o >>= 1) ls += __shfl_down_sync(0xffffffffu, ls, o);
    if (l == 0) s_red[w] = ls;
    __syncthreads();
    if (t == 0) {
        float sum = 0.0f;
#pragma unroll
        for (int i = 0; i < 8; ++i) sum += s_red[i];
        atomicAdd(&g_postsum[n], sum);
        __threadfence();
        unsigned prev = atomicAdd(&g_done, 1u);
        s_last = (prev == NBLK - 1) ? 1 : 0;
        if (s_last) g_done = 0;
    }
    __syncthreads();
    if (s_last && t < EE) {
        float mean = g_postsum[dst[t]] * (1.0f / (float)BCHW);
        outp[t] = plast[t] + 0.1f * (mean - 0.5f);
    }
}

// ---------------------------------------------------------------------------
extern "C" void kernel_launch(void* const* d_in, const int* in_sizes, int n_in,
                              void* d_out, int out_size) {
    const float* states  = (const float*)d_in[0];
    const float* weights = (const float*)d_in[1];
    const float* plast   = (const float*)d_in[2];
    const int*   src     = (const int*)d_in[3];
    const int*   dst     = (const int*)d_in[4];
    float* out = (float*)d_out;

    dim3 agrid(36, 400);
    act_prep_kernel<<<agrid, 256>>>(states, dst, plast);
    prepack_kernel<<<EE, 32>>>(weights);

    static int smem_set = 0;
    const int smem_bytes = 2 * ABUF * 4;     // 30976 B
    if (!smem_set) {
        cudaFuncSetAttribute(conv_mma_kernel,
                             cudaFuncAttributeMaxDynamicSharedMemorySize,
                             smem_bytes);
        smem_set = 1;
    }
    dim3 grid(NSEG, BB, NN);
    conv_mma_kernel<<<grid, 256, smem_bytes>>>(src, plast, dst, out,
                                               out + (out_size - EE));
}

// round 10
// speedup vs baseline: 2.0031x; 1.0286x over previous
#include <cuda_runtime.h>
#include <cuda_fp16.h>
#include <cstdint>

// Problem constants
#define NN   24
#define EE   96
#define BB   4
#define CC   8
#define HH   96
#define WW   96
#define KK   4
#define HW    (HH*WW)
#define CHW   (CC*HW)
#define BCHW  (BB*CHW)

// Padded fp16 activation scratch, ci-pair interleaved (+ tail pad for staging)
#define PH 100
#define PW 100
#define PLANE (PH*PW)            // 10000 words
#define NACTW (25*BB*4*PLANE + 4096)

// Conv-MMA tiling (fp16 m16n8k16, 2 kx taps per MMA, permuted rows)
#define SEGPX  1280              // pixels per block (80 m16 tiles)
#define NSEG   8                 // 8*1280 = 10240 >= 9600 (tail masked)
#define TPW    10                // m16 tiles per warp (8 warps)
#define WINW   1584              // window words per cpair plane
#define PSTR   1608              // cpair stride in words (==8 mod 32)
#define ABUF   (4*PSTR)          // 6432 words per stage buffer
#define PAIR4  396               // uint4 chunks per cpair window (1584/4)
#define NBLK   (NSEG*BB*NN)      // 768 conv blocks

__device__ __align__(16) unsigned int g_act[NACTW];
__device__ __align__(16) unsigned int g_bpack[EE * 32 * 16];
__device__ int   g_off[NN + 1];
__device__ int   g_elist[EE];
__device__ float g_escale[EE];
__device__ float g_postsum[NN];
__device__ unsigned int g_done;

__device__ __forceinline__ void mma_f16(float* d, uint32_t a0, uint32_t a1,
                                        uint32_t a2, uint32_t a3,
                                        uint32_t b0, uint32_t b1) {
    asm volatile(
        "mma.sync.aligned.m16n8k16.row.col.f32.f16.f16.f32 "
        "{%0,%1,%2,%3}, {%4,%5,%6,%7}, {%8,%9}, {%0,%1,%2,%3};"
        : "+f"(d[0]), "+f"(d[1]), "+f"(d[2]), "+f"(d[3])
        : "r"(a0), "r"(a1), "r"(a2), "r"(a3), "r"(b0), "r"(b1));
}

__device__ __forceinline__ void cpa16(uint32_t dst, const void* src) {
    asm volatile("cp.async.cg.shared.global [%0], [%1], 16;"
                 :: "r"(dst), "l"(src));
}
__device__ __forceinline__ uint32_t smem_u32(const void* p) {
    uint32_t a;
    asm("{ .reg .u64 t; cvta.to.shared.u64 t, %1; cvt.u32.u64 %0, t; }"
        : "=r"(a) : "l"(p));
    return a;
}
__device__ __forceinline__ uint32_t h2pack(float lo, float hi) {
    __half2 h = __floats2half2_rn(lo, hi);
    return *reinterpret_cast<uint32_t*>(&h);
}
// sigmoid via single-MUFU tanh.approx: sig(x) = 0.5*tanh(x/2) + 0.5
__device__ __forceinline__ float fast_sigmoid(float x) {
    float th;
    asm("tanh.approx.f32 %0, %1;" : "=f"(th) : "f"(x * 0.5f));
    return fmaf(th, 0.5f, 0.5f);
}

// ---------------------------------------------------------------------------
// Activation precompute (+ edge prep in block (0,0)). grid = (9, 400).
// Thread -> 4 consecutive pixels of one cpair plane.
// ---------------------------------------------------------------------------
__global__ __launch_bounds__(256)
void act_prep_kernel(const float* __restrict__ states,
                     const int* __restrict__ dst,
                     const float* __restrict__ plast) {
    const int t = threadIdx.x;
    if (blockIdx.x == 0 && blockIdx.y == 0) {
        __shared__ int cnt[NN];
        __shared__ int fill[NN];
        if (t < NN) { cnt[t] = 0; g_postsum[t] = 0.0f; }
        __syncthreads();
        if (t < EE) atomicAdd(&cnt[dst[t]], 1);
        __syncthreads();
        if (t == 0) {
            int off = 0;
            for (int n = 0; n < NN; ++n) { g_off[n] = off; fill[n] = off; off += cnt[n]; }
            g_off[NN] = off;
        }
        __syncthreads();
        if (t < EE) {
            int d = dst[t];
            int pos = atomicAdd(&fill[d], 1);
            g_elist[pos] = t;
            int deg = cnt[d] > 0 ? cnt[d] : 1;
            g_escale[t] = plast[t] / (float)deg;
        }
    }
    const int gp = blockIdx.y;              // group*4 + cp
    const int grp = gp >> 2;
    const int cp = gp & 3;
    const int pix = (blockIdx.x * 256 + t) * 4;   // 0..9212, 4-aligned
    const int r = pix / 96;
    const int c = pix - r * 96;

    const size_t base = (size_t)(grp * CC + 2 * cp) * HW + r * WW + c;
    const float4 zl = *reinterpret_cast<const float4*>(states + base);
    const float4 zh = *reinterpret_cast<const float4*>(states + base + HW);

    unsigned int* op = g_act + (size_t)gp * PLANE + (r + 1) * PW + 1 + c;
    op[0] = h2pack(fast_sigmoid(zl.x), fast_sigmoid(zh.x));
    op[1] = h2pack(fast_sigmoid(zl.y), fast_sigmoid(zh.y));
    op[2] = h2pack(fast_sigmoid(zl.z), fast_sigmoid(zh.z));
    op[3] = h2pack(fast_sigmoid(zl.w), fast_sigmoid(zh.w));
}

// ---------------------------------------------------------------------------
// B-fragment prepack (per edge, per lane, register order).
// ---------------------------------------------------------------------------
__global__ void prepack_kernel(const float* __restrict__ weights) {
    const int e = blockIdx.x;
    const int l = threadIdx.x;
    const int g = l >> 2;
    const int tg = l & 3;
    const float esc = g_escale[e];
    const float* wg = weights + (size_t)e * (CC * CC * KK * KK);
    const float4* rA = reinterpret_cast<const float4*>(wg + (g * CC + 2 * tg) * 16);
    const float4* rB = reinterpret_cast<const float4*>(wg + (g * CC + 2 * tg + 1) * 16);
    uint32_t o[16];
#pragma unroll
    for (int ky = 0; ky < 4; ++ky) {
        float4 a = rA[ky];
        float4 b = rB[ky];
        o[ky * 4 + 0] = h2pack(a.x * esc, b.x * esc);
        o[ky * 4 + 1] = h2pack(a.y * esc, b.y * esc);
        o[ky * 4 + 2] = h2pack(a.z * esc, b.z * esc);
        o[ky * 4 + 3] = h2pack(a.w * esc, b.w * esc);
    }
    uint4* dstp = reinterpret_cast<uint4*>(g_bpack + ((size_t)e * 32 + l) * 16);
#pragma unroll
    for (int j = 0; j < 4; ++j)
        dstp[j] = make_uint4(o[j * 4], o[j * 4 + 1], o[j * 4 + 2], o[j * 4 + 3]);
}

// ---------------------------------------------------------------------------
// Conv via fp16 m16n8k16 MMA, permuted rows. grid = (NSEG, B, N), 256 thr,
// 3 blocks/SM. Tail segment masked.
// ---------------------------------------------------------------------------
extern __shared__ unsigned int s_dynw[];

__global__ __launch_bounds__(256, 3)
void conv_mma_kernel(const int* __restrict__ src,
                     const float* __restrict__ plast,
                     const int* __restrict__ dst,
                     float* __restrict__ out,
                     float* __restrict__ outp) {
    const int seg = blockIdx.x;
    const int b = blockIdx.y;
    const int n = blockIdx.z;
    const int qbase = seg * SEGPX;

    __shared__ float s_red[8];
    __shared__ int s_last;
    unsigned int* s_win = s_dynw;
    const uint32_t s_win_u32 = smem_u32(s_win);

    const int t = threadIdx.x;
    const int w = t >> 5;
    const int l = t & 31;
    const int gid = l >> 2;
    const int tig = l & 3;

    float d[TPW][4];
#pragma unroll
    for (int u = 0; u < TPW; ++u)
#pragma unroll
        for (int j = 0; j < 4; ++j) d[u][j] = 0.0f;

    const int ebeg = g_off[n];
    const int eend = g_off[n + 1];

    auto stage = [&](int e, uint32_t dbase) {
        const int s = __ldg(&src[e]);
        const uint4* ap = reinterpret_cast<const uint4*>(
            g_act + ((size_t)(s * BB + b) * 4) * PLANE + qbase);
#pragma unroll
        for (int cp = 0; cp < 4; ++cp)
            for (int i = t; i < PAIR4; i += 256)
                cpa16(dbase + (cp * PSTR + i * 4) * 4,
                      ap + cp * (PLANE / 4) + i);
        asm volatile("cp.async.commit_group;");
    };

    stage(g_elist[ebeg], s_win_u32);

    for (int ei = ebeg; ei < eend; ++ei) {
        const int p = (ei - ebeg) & 1;
        const int e = g_elist[ei];

        const uint4* bp = reinterpret_cast<const uint4*>(
            g_bpack + ((size_t)e * 32 + l) * 16);
        uint4 bq[4];
#pragma unroll
        for (int ky = 0; ky < 4; ++ky) bq[ky] = __ldg(&bp[ky]);

        asm volatile("cp.async.wait_group 0;");
        __syncthreads();

        if (ei + 1 < eend)
            stage(g_elist[ei + 1], s_win_u32 + (1 - p) * (ABUF * 4));

        const unsigned int* fbase = s_win + p * ABUF + tig * PSTR + 2 * gid;
#pragma unroll
        for (int ky = 0; ky < KK; ++ky) {
            const uint32_t b00 = bq[ky].x, b01 = bq[ky].y;
            const uint32_t b10 = bq[ky].z, b11 = bq[ky].w;
#pragma unroll
            for (int kxp = 0; kxp < 2; ++kxp) {
                const uint32_t bb0 = kxp ? b10 : b00;
                const uint32_t bb1 = kxp ? b11 : b01;
                const int o = ky * PW + kxp * 2;
#pragma unroll
                for (int u = 0; u < TPW; ++u) {
                    const unsigned int* pa = fbase + (w * TPW + u) * 16 + o;
                    const uint2 v = *reinterpret_cast<const uint2*>(pa);
                    const uint32_t a3 = pa[2];
                    mma_f16(d[u], v.x, v.y, v.y, a3, bb0, bb1);
                }
            }
        }
    }

    // Epilogue: pixel pair (q0, q0+1); mask x<96 && y<96 (tail segment)
    float ls = 0.0f;
    const int co0 = tig * 2;
    float* outn = out + (size_t)((n * BB + b) * CC) * HW;
#pragma unroll
    for (int u = 0; u < TPW; ++u) {
        const int q0 = qbase + (w * TPW + u) * 16 + 2 * gid;
        const int y = q0 / PW;
        const int x = q0 - y * PW;
        if (x < WW && y < HH) {
            float v00 = d[u][0], v01 = d[u][1];
            float v10 = d[u][2], v11 = d[u][3];
            float* ob = outn + y * WW + x;
            ob[(size_t)co0 * HW] = v00;
            ob[(size_t)(co0 + 1) * HW] = v01;
            ob[(size_t)co0 * HW + 1] = v10;
            ob[(size_t)(co0 + 1) * HW + 1] = v11;
            ls += fast_sigmoid(v00);
            ls += fast_sigmoid(v01);
            ls += fast_sigmoid(v10);
            ls += fast_sigmoid(v11);
        }
    }
#pragma unroll
    for (int o = 16; o > 0; o >>= 1) ls += __shfl_down_sync(0xffffffffu, ls, o);
    if (l == 0) s_red[w] = ls;
    __syncthreads();
    if (t == 0) {
        float sum = 0.0f;
#pragma unroll
        for (int i = 0; i < 8; ++i) sum += s_red[i];
        atomicAdd(&g_postsum[n], sum);
        __threadfence();
        unsigned prev = atomicAdd(&g_done, 1u);
        s_last = (prev == NBLK - 1) ? 1 : 0;
        if (s_last) g_done = 0;
    }
    __syncthreads();
    if (s_last && t < EE) {
        float mean = g_postsum[dst[t]] * (1.0f / (float)BCHW);
        outp[t] = plast[t] + 0.1f * (mean - 0.5f);
    }
}

// ---------------------------------------------------------------------------
extern "C" void kernel_launch(void* const* d_in, const int* in_sizes, int n_in,
                              void* d_out, int out_size) {
    const float* states  = (const float*)d_in[0];
    const float* weights = (const float*)d_in[1];
    const float* plast   = (const float*)d_in[2];
    const int*   src     = (const int*)d_in[3];
    const int*   dst     = (const int*)d_in[4];
    float* out = (float*)d_out;

    dim3 agrid(9, 400);
    act_prep_kernel<<<agrid, 256>>>(states, dst, plast);
    prepack_kernel<<<EE, 32>>>(weights);

    static int smem_set = 0;
    const int smem_bytes = 2 * ABUF * 4;     // 51456 B
    if (!smem_set) {
        cudaFuncSetAttribute(conv_mma_kernel,
                             cudaFuncAttributeMaxDynamicSharedMemorySize,
                             smem_bytes);
        smem_set = 1;
    }
    dim3 grid(NSEG, BB, NN);
    conv_mma_kernel<<<grid, 256, smem_bytes>>>(src, plast, dst, out,
                                               out + (out_size - EE));
}